// round 7
// baseline (speedup 1.0000x reference)
#include <cuda_runtime.h>
#include <math.h>

// ---------------- problem constants (fixed by setup_inputs) ----------------
#define H   200
#define DT  48
#define DA  6
#define TT  20
#define BB  32768
#define CF  10

// ---------------- tiling ----------------
#define MT       64     // batch rows per block
#define NTHREADS 512    // 16 warps -> 4 per SMSP

// padded GEMM dims (k-major packed weights)
// stage1 A rows: pad(8) + x1(48) + h1(200)              = 256
// stage2 A rows: h1'(200) + tiled(48) + h2(200)         = 448
// stage3 A rows: pad(8) + x1(48) + h2'(200)             = 256  (reuses AsX)
// stage4 A rows: out3 padded                            = 224
#define K1 256
#define N1 1024         // 256 units * 4 gates (200 real)
#define K2 448
#define N2 1024
#define K3 256
#define N3 256          // fc1 out padded (200 real)
#define K4 224
#define N4 64           // fc2 out padded (48 real)

#define ASX_ROWS 256
#define AS2_ROWS 448
#define WS_FLOATS (32 * 256)
#define SMEM_FLOATS (ASX_ROWS*MT + AS2_ROWS*MT + WS_FLOATS)
#define SMEM_BYTES  (SMEM_FLOATS * 4)

typedef unsigned long long u64;

// ---------------- device scratch (no runtime allocation allowed) ----------
__device__ float g_WA[K1 * N1];
__device__ float g_WB[K2 * N2];
__device__ float g_WC[K3 * N3];
__device__ float g_WD[K4 * N4];
__device__ float g_bb1[N1];
__device__ float g_bb2[N2];
__device__ float g_b1p[N3];
__device__ float g_b2p[N4];
// h1, c1, h2, c2 each stored [H][B] (unit-major for coalesced staging)
__device__ float g_hc[(size_t)4 * H * BB];
// feedback x1 (previous out4), stored [DT][B]
__device__ float g_x1fb[(size_t)DT * BB];

// ---------------- fast transcendentals (ex2/rcp approx, ~1e-7 abs err) ----
__device__ __forceinline__ float fex2(float x) {
    float r; asm("ex2.approx.f32 %0, %1;" : "=f"(r) : "f"(x)); return r;
}
__device__ __forceinline__ float frcp(float x) {
    float r; asm("rcp.approx.f32 %0, %1;" : "=f"(r) : "f"(x)); return r;
}
#define L2E 1.4426950408889634f
__device__ __forceinline__ float sigf(float x) {
    return frcp(1.f + fex2(-L2E * x));
}
__device__ __forceinline__ float tanhff(float x) {
    return fmaf(2.f, frcp(1.f + fex2(-2.f * L2E * x)), -1.f);
}

// ---------------- packed f32x2 helpers ------------------------------------
__device__ __forceinline__ u64 pk2(float lo, float hi) {
    u64 r; asm("mov.b64 %0, {%1,%2};" : "=l"(r) : "f"(lo), "f"(hi)); return r;
}
__device__ __forceinline__ float2 up2(u64 v) {
    float2 r; asm("mov.b64 {%0,%1}, %2;" : "=f"(r.x), "=f"(r.y) : "l"(v)); return r;
}
__device__ __forceinline__ void ffma2(u64& d, u64 a, u64 b) {
    asm("fma.rn.f32x2 %0, %1, %2, %0;" : "+l"(d) : "l"(a), "l"(b));
}

// ---------------- weight repack kernel (runs once per kernel_launch) ------
__global__ void prep_kernel(
    const float* __restrict__ Wih1, const float* __restrict__ Whh1,
    const float* __restrict__ bih1, const float* __restrict__ bhh1,
    const float* __restrict__ Wih2, const float* __restrict__ Whh2,
    const float* __restrict__ bih2, const float* __restrict__ bhh2,
    const float* __restrict__ W1,   const float* __restrict__ b1,
    const float* __restrict__ W2,   const float* __restrict__ b2)
{
    int idx    = blockIdx.x * blockDim.x + threadIdx.x;
    int stride = gridDim.x * blockDim.x;

    // WA: [K1][N1] k-major, gate-interleaved cols: col = u*4+g
    // k-order: pad(8), x1(48), h1(200)
    for (int i = idx; i < K1 * N1; i += stride) {
        int k = i / N1, col = i % N1;
        int u = col >> 2, g = col & 3;
        float v = 0.f;
        if (u < H) {
            int row = g * H + u;
            if (k >= 8 && k < 8 + DT)            v = Wih1[row * DT + (k - 8)];
            else if (k >= 56 && k < 56 + H)      v = Whh1[row * H + (k - 56)];
        }
        g_WA[i] = v;
    }
    // WB: [K2][N2]; A-order = [h1'(200), tiled(48), h2(200)]
    for (int i = idx; i < K2 * N2; i += stride) {
        int k = i / N2, col = i % N2;
        int u = col >> 2, g = col & 3;
        float v = 0.f;
        if (u < H) {
            int row = g * H + u;
            if (k < H + DT) v = Wih2[row * (H + DT) + k];
            else            v = Whh2[row * H + (k - (H + DT))];
        }
        g_WB[i] = v;
    }
    // WC: [K3][N3]; A-order = [pad(8), x1(48), h2'(200)];
    // W1 cols ordered [h2(200), x1(48)]
    for (int i = idx; i < K3 * N3; i += stride) {
        int k = i / N3, n = i % N3;
        float v = 0.f;
        if (n < H) {
            if (k >= 8 && k < 8 + DT)        v = W1[n * (H + DT) + H + (k - 8)];
            else if (k >= 56 && k < 56 + H)  v = W1[n * (H + DT) + (k - 56)];
        }
        g_WC[i] = v;
    }
    // WD: [K4][N4]
    for (int i = idx; i < K4 * N4; i += stride) {
        int k = i / N4, n = i % N4;
        float v = 0.f;
        if (n < DT && k < H) v = W2[n * H + k];
        g_WD[i] = v;
    }
    // biases
    for (int i = idx; i < N1; i += stride) {
        int u = i >> 2, g = i & 3;
        float v1 = 0.f, v2 = 0.f;
        if (u < H) {
            v1 = bih1[g * H + u] + bhh1[g * H + u];
            v2 = bih2[g * H + u] + bhh2[g * H + u];
        }
        g_bb1[i] = v1;
        g_bb2[i] = v2;
    }
    for (int i = idx; i < N3; i += stride) g_b1p[i] = (i < H)  ? b1[i] : 0.f;
    for (int i = idx; i < N4; i += stride) g_b2p[i] = (i < DT) ? b2[i] : 0.f;
}

__global__ void zero_hc_kernel() {
    size_t n = (size_t)4 * H * BB;
    for (size_t i = blockIdx.x * (size_t)blockDim.x + threadIdx.x; i < n;
         i += (size_t)gridDim.x * blockDim.x)
        g_hc[i] = 0.f;
}

// ---------------- block GEMM pass (f32x2 packed) --------------------------
// A: smem [K][MT] k-major. Wg: global [K][ldw] k-major. Computes 64*CPT
// columns starting at colBase. Thread owns rows m0..m0+7 (4 f32x2 pairs)
// and cols cg*CPT..cg*CPT+CPT-1. All 32 lanes of a warp share m0 -> A loads
// are warp-broadcast; W loads are 16B/lane conflict-free.
template <int CPT>
__device__ __forceinline__ void gemm_pass(
    const float* __restrict__ A, const float* __restrict__ Wg,
    int K, int ldw, int colBase, float* __restrict__ Ws,
    u64 (&acc)[4][CPT], int m0, int cg, int tid)
{
    constexpr int NC = 64 * CPT;
    constexpr int LD_ITERS = NC / 64;   // (32*NC) / (NTHREADS*4)

#pragma unroll
    for (int i = 0; i < 4; i++)
#pragma unroll
        for (int j = 0; j < CPT; j++) acc[i][j] = 0ULL;

    for (int k0 = 0; k0 < K; k0 += 32) {
        __syncthreads();  // Ws reuse + prior smem writes visible
#pragma unroll
        for (int it = 0; it < LD_ITERS; it++) {
            int idx = tid * 4 + it * (NTHREADS * 4);
            int kk = idx / NC, c = idx % NC;
            *(float4*)(Ws + idx) =
                *(const float4*)(Wg + (size_t)(k0 + kk) * ldw + colBase + c);
        }
        __syncthreads();
#pragma unroll
        for (int kk = 0; kk < 32; kk++) {
            const float* Ar = A + (k0 + kk) * MT + m0;
            double2 q0 = *(const double2*)(Ar + 0);
            double2 q1 = *(const double2*)(Ar + 4);
            u64 ap[4] = {
                __double_as_longlong(q0.x), __double_as_longlong(q0.y),
                __double_as_longlong(q1.x), __double_as_longlong(q1.y)};
            u64 wp[CPT];
            const float* Wr = Ws + kk * NC + cg * CPT;
            if (CPT == 4) {
                float4 wv = *(const float4*)Wr;
                wp[0] = pk2(wv.x, wv.x); wp[1] = pk2(wv.y, wv.y);
                wp[2] = pk2(wv.z, wv.z); wp[3] = pk2(wv.w, wv.w);
            } else {
                float wv = Wr[0];
                wp[0] = pk2(wv, wv);
            }
#pragma unroll
            for (int i = 0; i < 4; i++)
#pragma unroll
                for (int j = 0; j < CPT; j++) ffma2(acc[i][j], ap[i], wp[j]);
        }
    }
}

// ---------------- LSTM gate epilogue (one unit, 8 rows) -------------------
__device__ __forceinline__ void lstm_epi(
    u64 (&acc)[4][4], const float* __restrict__ bb,
    float* __restrict__ cgl, float* __restrict__ hgl,
    float* __restrict__ hdst, int u, int row0, int m0)
{
    float4 b = *(const float4*)(bb + u * 4);  // i,f,g,o
    size_t base = (size_t)u * BB + row0 + m0;
#pragma unroll
    for (int i = 0; i < 4; i++) {
        float2 zi = up2(acc[i][0]);
        float2 zf = up2(acc[i][1]);
        float2 zg = up2(acc[i][2]);
        float2 zo = up2(acc[i][3]);
        float2 c = *(const float2*)(cgl + base + 2 * i);
        float cx = sigf(zf.x + b.y) * c.x + sigf(zi.x + b.x) * tanhff(zg.x + b.z);
        float cy = sigf(zf.y + b.y) * c.y + sigf(zi.y + b.x) * tanhff(zg.y + b.z);
        float hx = sigf(zo.x + b.w) * tanhff(cx);
        float hy = sigf(zo.y + b.w) * tanhff(cy);
        *(float2*)(cgl + base + 2 * i) = make_float2(cx, cy);
        *(float2*)(hgl + base + 2 * i) = make_float2(hx, hy);
        *(float2*)(hdst + u * MT + m0 + 2 * i) = make_float2(hx, hy);
    }
}

// ---------------- fused per-timestep kernel -------------------------------
__global__ void __launch_bounds__(NTHREADS, 1)
step_kernel(const float* __restrict__ tact, const float* __restrict__ act,
            float* __restrict__ out, int t, int outFrame, int useFb)
{
    extern __shared__ float sm[];
    float* AsX = sm;                      // [256][MT]
    float* As2 = sm + ASX_ROWS * MT;      // [448][MT]
    float* Ws  = As2 + AS2_ROWS * MT;     // [32][256]

    int tid  = threadIdx.x;
    int w    = tid >> 5, lane = tid & 31;
    int m0   = (w & 7) * 8;               // row group (8 rows, 4 pairs)
    int cg   = ((w >> 3) << 5) + lane;    // col group 0..63
    int row0 = blockIdx.x * MT;

    float* h1g = g_hc;
    float* c1g = g_hc + (size_t)1 * H * BB;
    float* h2g = g_hc + (size_t)2 * H * BB;
    float* c2g = g_hc + (size_t)3 * H * BB;

    // -------- stage A operands --------
    // AsX rows 0..8 = 0 (pad)
    for (int idx = tid; idx < 8 * MT; idx += NTHREADS) AsX[idx] = 0.f;
    // AsX rows 8..56 = x1 (tactile or feedback)
    for (int idx = tid; idx < DT * MT; idx += NTHREADS) {
        int d = idx / MT, r = idx % MT;
        float v = useFb ? g_x1fb[(size_t)d * BB + row0 + r]
                        : tact[(size_t)t * BB * DT + (size_t)(row0 + r) * DT + d];
        AsX[(8 + d) * MT + r] = v;
    }
    // AsX rows 56..256 = h1
    for (int idx = tid; idx < H * MT; idx += NTHREADS) {
        int u = idx / MT, r = idx % MT;
        AsX[(56 + u) * MT + r] = h1g[(size_t)u * BB + row0 + r];
    }
    // As2 rows 200..248 = tiled(act) = [a(6), state(6)] x4
    for (int idx = tid; idx < DT * MT; idx += NTHREADS) {
        int j = idx / MT, r = idx % MT;
        int jm = j % 12;
        float v = (jm < 6)
            ? act[(size_t)(t + 1) * BB * DA + (size_t)(row0 + r) * DA + jm]
            : act[(size_t)(row0 + r) * DA + (jm - 6)];
        As2[(H + j) * MT + r] = v;
    }
    // As2 rows 248..448 = h2
    for (int idx = tid; idx < H * MT; idx += NTHREADS) {
        int u = idx / MT, r = idx % MT;
        As2[(H + DT + u) * MT + r] = h2g[(size_t)u * BB + row0 + r];
    }

    u64 acc[4][4];

    // -------- stage 1: z1 GEMM + LSTM1 gates (h1' -> As2 rows 0..200) -----
    for (int p = 0; p < 4; p++) {
        gemm_pass<4>(AsX, g_WA, K1, N1, p * 256, Ws, acc, m0, cg, tid);
        int u = p * 64 + cg;
        if (u < H) lstm_epi(acc, g_bb1, c1g, h1g, As2, u, row0, m0);
    }

    // -------- stage 2: z2 GEMM + LSTM2 gates (h2' -> AsX rows 56..256) ----
    for (int p = 0; p < 4; p++) {
        gemm_pass<4>(As2, g_WB, K2, N2, p * 256, Ws, acc, m0, cg, tid);
        int u = p * 64 + cg;
        if (u < H) lstm_epi(acc, g_bb2, c2g, h2g, AsX + 56 * MT, u, row0, m0);
    }

    // -------- stage 3: fc1 + tanh (out3 -> As2 rows 0..224) ---------------
    gemm_pass<4>(AsX, g_WC, K3, N3, 0, Ws, acc, m0, cg, tid);
#pragma unroll
    for (int j = 0; j < 4; j++) {
        int n = cg * 4 + j;
        if (n < K4) {   // rows 200..224 get exact zeros (zero W cols, zero bias)
            float b = g_b1p[n];
#pragma unroll
            for (int i = 0; i < 4; i++) {
                float2 z = up2(acc[i][j]);
                *(float2*)(As2 + n * MT + m0 + 2 * i) =
                    make_float2(tanhff(z.x + b), tanhff(z.y + b));
            }
        }
    }

    // -------- stage 4: fc2 + tanh, write outputs --------------------------
    u64 acc1[4][1];
    gemm_pass<1>(As2, g_WD, K4, N4, 0, Ws, acc1, m0, cg, tid);
    {
        int n = cg;
        if (n < DT) {
            float b = g_b2p[n];
#pragma unroll
            for (int i = 0; i < 4; i++) {
                float2 z = up2(acc1[i][0]);
                float vx = tanhff(z.x + b);
                float vy = tanhff(z.y + b);
                int rg = row0 + m0 + 2 * i;
                *(float2*)(g_x1fb + (size_t)n * BB + rg) = make_float2(vx, vy);
                if (outFrame >= 0) {
                    out[((size_t)outFrame * BB + rg) * DT + n]     = vx;
                    out[((size_t)outFrame * BB + rg + 1) * DT + n] = vy;
                }
            }
        }
    }
}

// ---------------- host launcher -----------------------------------------
extern "C" void kernel_launch(void* const* d_in, const int* in_sizes, int n_in,
                              void* d_out, int out_size) {
    const float* tactiles = (const float*)d_in[0];
    const float* actions  = (const float*)d_in[1];
    const float* Wih1 = (const float*)d_in[2];
    const float* Whh1 = (const float*)d_in[3];
    const float* bih1 = (const float*)d_in[4];
    const float* bhh1 = (const float*)d_in[5];
    const float* Wih2 = (const float*)d_in[6];
    const float* Whh2 = (const float*)d_in[7];
    const float* bih2 = (const float*)d_in[8];
    const float* bhh2 = (const float*)d_in[9];
    const float* W1   = (const float*)d_in[10];
    const float* b1   = (const float*)d_in[11];
    const float* W2   = (const float*)d_in[12];
    const float* b2   = (const float*)d_in[13];
    float* out = (float*)d_out;

    cudaFuncSetAttribute(step_kernel,
                         cudaFuncAttributeMaxDynamicSharedMemorySize, SMEM_BYTES);

    zero_hc_kernel<<<2048, 256>>>();
    prep_kernel<<<512, 256>>>(Wih1, Whh1, bih1, bhh1,
                              Wih2, Whh2, bih2, bhh2, W1, b1, W2, b2);

    for (int t = 0; t < TT - 1; t++) {
        int useFb    = (t >= CF) ? 1 : 0;
        int outFrame = (t >= CF - 1) ? (t - (CF - 1)) : -1;
        step_kernel<<<BB / MT, NTHREADS, SMEM_BYTES>>>(
            tactiles, actions, out, t, outFrame, useFb);
    }
}

// round 8
// speedup vs baseline: 1.0176x; 1.0176x over previous
#include <cuda_runtime.h>
#include <math.h>

// ---------------- problem constants (fixed by setup_inputs) ----------------
#define H   200
#define DT  48
#define DA  6
#define TT  20
#define BB  32768
#define CF  10

// ---------------- tiling ----------------
#define MT       64     // batch rows per block
#define NTHREADS 512    // 16 warps -> 4 per SMSP

// padded GEMM dims (k-major packed weights)
// stage1 A rows: pad(8) + x1(48) + h1(200)              = 256
// stage2 A rows: h1'(200) + tiled(48) + h2(200)         = 448
// stage3 A rows: pad(8) + x1(48) + h2'(200)             = 256  (reuses AsX)
// stage4 A rows: out3 padded                            = 224
#define K1 256
#define N1 1024         // 256 units * 4 gates (200 real)
#define K2 448
#define N2 1024
#define K3 256
#define N3 256          // fc1 out padded (200 real)
#define K4 224
#define N4 64           // fc2 out padded (48 real)

#define ASX_ROWS 256
#define AS2_ROWS 448
#define WS_FLOATS (32 * 256)
#define SMEM_FLOATS (ASX_ROWS*MT + AS2_ROWS*MT + WS_FLOATS)
#define SMEM_BYTES  (SMEM_FLOATS * 4)

typedef unsigned long long u64;

// ---------------- device scratch (no runtime allocation allowed) ----------
__device__ float g_WA[K1 * N1];
__device__ float g_WB[K2 * N2];
__device__ float g_WC[K3 * N3];
__device__ float g_WD[K4 * N4];
__device__ float g_bb1[N1];
__device__ float g_bb2[N2];
__device__ float g_b1p[N3];
__device__ float g_b2p[N4];
// h1, c1, h2, c2 each stored [H][B] (unit-major for coalesced staging)
__device__ float g_hc[(size_t)4 * H * BB];
// feedback x1 (previous out4), stored [DT][B]
__device__ float g_x1fb[(size_t)DT * BB];

// ---------------- fast transcendentals (ex2/rcp approx, ~1e-7 abs err) ----
__device__ __forceinline__ float fex2(float x) {
    float r; asm("ex2.approx.f32 %0, %1;" : "=f"(r) : "f"(x)); return r;
}
__device__ __forceinline__ float frcp(float x) {
    float r; asm("rcp.approx.f32 %0, %1;" : "=f"(r) : "f"(x)); return r;
}
#define L2E 1.4426950408889634f
__device__ __forceinline__ float sigf(float x) {
    return frcp(1.f + fex2(-L2E * x));
}
__device__ __forceinline__ float tanhff(float x) {
    return fmaf(2.f, frcp(1.f + fex2(-2.f * L2E * x)), -1.f);
}

// ---------------- packed f32x2 helpers ------------------------------------
__device__ __forceinline__ u64 pk2(float lo, float hi) {
    u64 r; asm("mov.b64 %0, {%1,%2};" : "=l"(r) : "f"(lo), "f"(hi)); return r;
}
__device__ __forceinline__ float2 up2(u64 v) {
    float2 r; asm("mov.b64 {%0,%1}, %2;" : "=f"(r.x), "=f"(r.y) : "l"(v)); return r;
}
__device__ __forceinline__ void ffma2(u64& d, u64 a, u64 b) {
    asm("fma.rn.f32x2 %0, %1, %2, %0;" : "+l"(d) : "l"(a), "l"(b));
}

// ---------------- weight repack kernel (runs once per kernel_launch) ------
__global__ void prep_kernel(
    const float* __restrict__ Wih1, const float* __restrict__ Whh1,
    const float* __restrict__ bih1, const float* __restrict__ bhh1,
    const float* __restrict__ Wih2, const float* __restrict__ Whh2,
    const float* __restrict__ bih2, const float* __restrict__ bhh2,
    const float* __restrict__ W1,   const float* __restrict__ b1,
    const float* __restrict__ W2,   const float* __restrict__ b2)
{
    int idx    = blockIdx.x * blockDim.x + threadIdx.x;
    int stride = gridDim.x * blockDim.x;

    // WA: [K1][N1] k-major, gate-interleaved cols: col = u*4+g
    // k-order: pad(8), x1(48), h1(200)
    for (int i = idx; i < K1 * N1; i += stride) {
        int k = i / N1, col = i % N1;
        int u = col >> 2, g = col & 3;
        float v = 0.f;
        if (u < H) {
            int row = g * H + u;
            if (k >= 8 && k < 8 + DT)            v = Wih1[row * DT + (k - 8)];
            else if (k >= 56 && k < 56 + H)      v = Whh1[row * H + (k - 56)];
        }
        g_WA[i] = v;
    }
    // WB: [K2][N2]; A-order = [h1'(200), tiled(48), h2(200)]
    for (int i = idx; i < K2 * N2; i += stride) {
        int k = i / N2, col = i % N2;
        int u = col >> 2, g = col & 3;
        float v = 0.f;
        if (u < H) {
            int row = g * H + u;
            if (k < H + DT) v = Wih2[row * (H + DT) + k];
            else            v = Whh2[row * H + (k - (H + DT))];
        }
        g_WB[i] = v;
    }
    // WC: [K3][N3]; A-order = [pad(8), x1(48), h2'(200)];
    // W1 cols ordered [h2(200), x1(48)]
    for (int i = idx; i < K3 * N3; i += stride) {
        int k = i / N3, n = i % N3;
        float v = 0.f;
        if (n < H) {
            if (k >= 8 && k < 8 + DT)        v = W1[n * (H + DT) + H + (k - 8)];
            else if (k >= 56 && k < 56 + H)  v = W1[n * (H + DT) + (k - 56)];
        }
        g_WC[i] = v;
    }
    // WD: [K4][N4]
    for (int i = idx; i < K4 * N4; i += stride) {
        int k = i / N4, n = i % N4;
        float v = 0.f;
        if (n < DT && k < H) v = W2[n * H + k];
        g_WD[i] = v;
    }
    // biases
    for (int i = idx; i < N1; i += stride) {
        int u = i >> 2, g = i & 3;
        float v1 = 0.f, v2 = 0.f;
        if (u < H) {
            v1 = bih1[g * H + u] + bhh1[g * H + u];
            v2 = bih2[g * H + u] + bhh2[g * H + u];
        }
        g_bb1[i] = v1;
        g_bb2[i] = v2;
    }
    for (int i = idx; i < N3; i += stride) g_b1p[i] = (i < H)  ? b1[i] : 0.f;
    for (int i = idx; i < N4; i += stride) g_b2p[i] = (i < DT) ? b2[i] : 0.f;
}

__global__ void zero_hc_kernel() {
    size_t n = (size_t)4 * H * BB;
    for (size_t i = blockIdx.x * (size_t)blockDim.x + threadIdx.x; i < n;
         i += (size_t)gridDim.x * blockDim.x)
        g_hc[i] = 0.f;
}

// ---------------- block GEMM pass (f32x2 packed) --------------------------
// A: smem [K][MT] k-major. Wg: global [K][ldw] k-major. Computes 64*CPT
// columns starting at colBase. Thread owns rows m0..m0+7 (4 f32x2 pairs)
// and cols cg*CPT..cg*CPT+CPT-1. All 32 lanes of a warp share m0 -> A loads
// are warp-broadcast; W loads are 16B/lane conflict-free.
template <int CPT>
__device__ __forceinline__ void gemm_pass(
    const float* __restrict__ A, const float* __restrict__ Wg,
    int K, int ldw, int colBase, float* __restrict__ Ws,
    u64 (&acc)[4][CPT], int m0, int cg, int tid)
{
    constexpr int NC = 64 * CPT;
    constexpr int LD_ITERS = NC / 64;   // (32*NC) / (NTHREADS*4)

#pragma unroll
    for (int i = 0; i < 4; i++)
#pragma unroll
        for (int j = 0; j < CPT; j++) acc[i][j] = 0ULL;

    for (int k0 = 0; k0 < K; k0 += 32) {
        __syncthreads();  // Ws reuse + prior smem writes visible
#pragma unroll
        for (int it = 0; it < LD_ITERS; it++) {
            int idx = tid * 4 + it * (NTHREADS * 4);
            int kk = idx / NC, c = idx % NC;
            *(float4*)(Ws + idx) =
                *(const float4*)(Wg + (size_t)(k0 + kk) * ldw + colBase + c);
        }
        __syncthreads();
#pragma unroll
        for (int kk = 0; kk < 32; kk++) {
            const float* Ar = A + (k0 + kk) * MT + m0;
            double2 q0 = *(const double2*)(Ar + 0);
            double2 q1 = *(const double2*)(Ar + 4);
            u64 ap[4] = {
                __double_as_longlong(q0.x), __double_as_longlong(q0.y),
                __double_as_longlong(q1.x), __double_as_longlong(q1.y)};
            u64 wp[CPT];
            const float* Wr = Ws + kk * NC + cg * CPT;
            if (CPT == 4) {
                float4 wv = *(const float4*)Wr;
                wp[0] = pk2(wv.x, wv.x); wp[1] = pk2(wv.y, wv.y);
                wp[2] = pk2(wv.z, wv.z); wp[3] = pk2(wv.w, wv.w);
            } else {
                float wv = Wr[0];
                wp[0] = pk2(wv, wv);
            }
#pragma unroll
            for (int i = 0; i < 4; i++)
#pragma unroll
                for (int j = 0; j < CPT; j++) ffma2(acc[i][j], ap[i], wp[j]);
        }
    }
}

// ---------------- LSTM gate epilogue (one unit, 8 rows) -------------------
__device__ __forceinline__ void lstm_epi(
    u64 (&acc)[4][4], const float* __restrict__ bb,
    float* __restrict__ cgl, float* __restrict__ hgl,
    float* __restrict__ hdst, int u, int row0, int m0)
{
    float4 b = *(const float4*)(bb + u * 4);  // i,f,g,o
    size_t base = (size_t)u * BB + row0 + m0;
#pragma unroll
    for (int i = 0; i < 4; i++) {
        float2 zi = up2(acc[i][0]);
        float2 zf = up2(acc[i][1]);
        float2 zg = up2(acc[i][2]);
        float2 zo = up2(acc[i][3]);
        float2 c = *(const float2*)(cgl + base + 2 * i);
        float cx = sigf(zf.x + b.y) * c.x + sigf(zi.x + b.x) * tanhff(zg.x + b.z);
        float cy = sigf(zf.y + b.y) * c.y + sigf(zi.y + b.x) * tanhff(zg.y + b.z);
        float hx = sigf(zo.x + b.w) * tanhff(cx);
        float hy = sigf(zo.y + b.w) * tanhff(cy);
        *(float2*)(cgl + base + 2 * i) = make_float2(cx, cy);
        *(float2*)(hgl + base + 2 * i) = make_float2(hx, hy);
        *(float2*)(hdst + u * MT + m0 + 2 * i) = make_float2(hx, hy);
    }
}

// ---------------- fused per-timestep kernel -------------------------------
__global__ void __launch_bounds__(NTHREADS, 1)
step_kernel(const float* __restrict__ tact, const float* __restrict__ act,
            float* __restrict__ out, int t, int outFrame, int useFb)
{
    extern __shared__ float sm[];
    float* AsX = sm;                      // [256][MT]
    float* As2 = sm + ASX_ROWS * MT;      // [448][MT]
    float* Ws  = As2 + AS2_ROWS * MT;     // [32][256]

    int tid  = threadIdx.x;
    int w    = tid >> 5, lane = tid & 31;
    int m0   = (w & 7) * 8;               // row group (8 rows, 4 pairs)
    int cg   = ((w >> 3) << 5) + lane;    // col group 0..63
    int row0 = blockIdx.x * MT;

    float* h1g = g_hc;
    float* c1g = g_hc + (size_t)1 * H * BB;
    float* h2g = g_hc + (size_t)2 * H * BB;
    float* c2g = g_hc + (size_t)3 * H * BB;

    // -------- stage A operands --------
    // AsX rows 0..8 = 0 (pad)
    for (int idx = tid; idx < 8 * MT; idx += NTHREADS) AsX[idx] = 0.f;
    // AsX rows 8..56 = x1 (tactile or feedback)
    for (int idx = tid; idx < DT * MT; idx += NTHREADS) {
        int d = idx / MT, r = idx % MT;
        float v = useFb ? g_x1fb[(size_t)d * BB + row0 + r]
                        : tact[(size_t)t * BB * DT + (size_t)(row0 + r) * DT + d];
        AsX[(8 + d) * MT + r] = v;
    }
    // AsX rows 56..256 = h1
    for (int idx = tid; idx < H * MT; idx += NTHREADS) {
        int u = idx / MT, r = idx % MT;
        AsX[(56 + u) * MT + r] = h1g[(size_t)u * BB + row0 + r];
    }
    // As2 rows 200..248 = tiled(act) = [a(6), state(6)] x4
    for (int idx = tid; idx < DT * MT; idx += NTHREADS) {
        int j = idx / MT, r = idx % MT;
        int jm = j % 12;
        float v = (jm < 6)
            ? act[(size_t)(t + 1) * BB * DA + (size_t)(row0 + r) * DA + jm]
            : act[(size_t)(row0 + r) * DA + (jm - 6)];
        As2[(H + j) * MT + r] = v;
    }
    // As2 rows 248..448 = h2
    for (int idx = tid; idx < H * MT; idx += NTHREADS) {
        int u = idx / MT, r = idx % MT;
        As2[(H + DT + u) * MT + r] = h2g[(size_t)u * BB + row0 + r];
    }

    u64 acc[4][4];

    // -------- stage 1: z1 GEMM + LSTM1 gates (h1' -> As2 rows 0..200) -----
    for (int p = 0; p < 4; p++) {
        gemm_pass<4>(AsX, g_WA, K1, N1, p * 256, Ws, acc, m0, cg, tid);
        int u = p * 64 + cg;
        if (u < H) lstm_epi(acc, g_bb1, c1g, h1g, As2, u, row0, m0);
    }

    // -------- stage 2: z2 GEMM + LSTM2 gates (h2' -> AsX rows 56..256) ----
    for (int p = 0; p < 4; p++) {
        gemm_pass<4>(As2, g_WB, K2, N2, p * 256, Ws, acc, m0, cg, tid);
        int u = p * 64 + cg;
        if (u < H) lstm_epi(acc, g_bb2, c2g, h2g, AsX + 56 * MT, u, row0, m0);
    }

    // -------- stage 3: fc1 + tanh (out3 -> As2 rows 0..224) ---------------
    gemm_pass<4>(AsX, g_WC, K3, N3, 0, Ws, acc, m0, cg, tid);
#pragma unroll
    for (int j = 0; j < 4; j++) {
        int n = cg * 4 + j;
        if (n < K4) {   // rows 200..224 get exact zeros (zero W cols, zero bias)
            float b = g_b1p[n];
#pragma unroll
            for (int i = 0; i < 4; i++) {
                float2 z = up2(acc[i][j]);
                *(float2*)(As2 + n * MT + m0 + 2 * i) =
                    make_float2(tanhff(z.x + b), tanhff(z.y + b));
            }
        }
    }

    // -------- stage 4: fc2 + tanh, write outputs --------------------------
    u64 acc1[4][1];
    gemm_pass<1>(As2, g_WD, K4, N4, 0, Ws, acc1, m0, cg, tid);
    {
        int n = cg;
        if (n < DT) {
            float b = g_b2p[n];
#pragma unroll
            for (int i = 0; i < 4; i++) {
                float2 z = up2(acc1[i][0]);
                float vx = tanhff(z.x + b);
                float vy = tanhff(z.y + b);
                int rg = row0 + m0 + 2 * i;
                *(float2*)(g_x1fb + (size_t)n * BB + rg) = make_float2(vx, vy);
                if (outFrame >= 0) {
                    out[((size_t)outFrame * BB + rg) * DT + n]     = vx;
                    out[((size_t)outFrame * BB + rg + 1) * DT + n] = vy;
                }
            }
        }
    }
}

// ---------------- host launcher -----------------------------------------
extern "C" void kernel_launch(void* const* d_in, const int* in_sizes, int n_in,
                              void* d_out, int out_size) {
    const float* tactiles = (const float*)d_in[0];
    const float* actions  = (const float*)d_in[1];
    const float* Wih1 = (const float*)d_in[2];
    const float* Whh1 = (const float*)d_in[3];
    const float* bih1 = (const float*)d_in[4];
    const float* bhh1 = (const float*)d_in[5];
    const float* Wih2 = (const float*)d_in[6];
    const float* Whh2 = (const float*)d_in[7];
    const float* bih2 = (const float*)d_in[8];
    const float* bhh2 = (const float*)d_in[9];
    const float* W1   = (const float*)d_in[10];
    const float* b1   = (const float*)d_in[11];
    const float* W2   = (const float*)d_in[12];
    const float* b2   = (const float*)d_in[13];
    float* out = (float*)d_out;

    cudaFuncSetAttribute(step_kernel,
                         cudaFuncAttributeMaxDynamicSharedMemorySize, SMEM_BYTES);

    zero_hc_kernel<<<2048, 256>>>();
    prep_kernel<<<512, 256>>>(Wih1, Whh1, bih1, bhh1,
                              Wih2, Whh2, bih2, bhh2, W1, b1, W2, b2);

    for (int t = 0; t < TT - 1; t++) {
        int useFb    = (t >= CF) ? 1 : 0;
        int outFrame = (t >= CF - 1) ? (t - (CF - 1)) : -1;
        step_kernel<<<BB / MT, NTHREADS, SMEM_BYTES>>>(
            tactiles, actions, out, t, outFrame, useFb);
    }
}